// round 14
// baseline (speedup 1.0000x reference)
#include <cuda_runtime.h>
#include <cuda_bf16.h>
typedef unsigned short ush;

#define RB   64
#define NTH  512
#define ASTR 808
#define KC   34
#define NMM  11
#define NEGBIG -1000000000.0f

__device__ uint4 g_Bp[KC*64*32];
__device__ uint4 g_wz4[1024*2*8*512];
__device__ float g_G4[4*16*1024];
__device__ float g_ent[2];

__device__ __forceinline__ unsigned su32(const void* p){
  unsigned r; asm("{.reg .u64 t; cvta.to.shared.u64 t, %1; cvt.u32.u64 %0, t;}" : "=r"(r) : "l"(p)); return r; }
__device__ __forceinline__ ush f2b(float x){ return __bfloat16_as_ushort(__float2bfloat16_rn(x)); }
__device__ __forceinline__ float b2f(ush u){ return __bfloat162float(__ushort_as_bfloat16(u)); }
__device__ __forceinline__ float tanha(float x){ float y; asm("tanh.approx.f32 %0, %1;" : "=f"(y) : "f"(x)); return y; }
__device__ __forceinline__ float sigf(float x){ return fmaf(0.5f, tanha(0.5f*x), 0.5f); }
__device__ __forceinline__ unsigned pk2f(float lo,float hi){
  return (unsigned)__bfloat16_as_ushort(__float2bfloat16_rn(lo)) |
         ((unsigned)__bfloat16_as_ushort(__float2bfloat16_rn(hi))<<16); }
__device__ __forceinline__ float xlo(unsigned u){ return __uint_as_float(u<<16); }
__device__ __forceinline__ float xhi(unsigned u){ return __uint_as_float(u & 0xffff0000u); }

#define LDSM4(r0,r1,r2,r3,a) asm volatile( \
  "ldmatrix.sync.aligned.m8n8.x4.shared.b16 {%0,%1,%2,%3},[%4];" \
  : "=r"(r0),"=r"(r1),"=r"(r2),"=r"(r3) : "r"(a))
#define MMA(d,a0,a1,a2,a3,b0,b1) asm( \
  "mma.sync.aligned.m16n8k16.row.col.f32.bf16.bf16.f32 {%0,%1,%2,%3},{%4,%5,%6,%7},{%8,%9},{%0,%1,%2,%3};" \
  : "+f"(d[0]),"+f"(d[1]),"+f"(d[2]),"+f"(d[3]) : "r"(a0),"r"(a1),"r"(a2),"r"(a3),"r"(b0),"r"(b1))

__device__ float wval(int k,int grow,const float* Wih,const float* Whh){
  if (k<256) return Wih[grow*448+k];
  if (k<512) return Whh[grow*256+(k-256)];
  return 0.f;
}

__global__ void prep_bfrag(const float* Wih,const float* Whh){
  int idx = blockIdx.x*blockDim.x + threadIdx.x;
  if (idx==0){ g_ent[0]=0.f; g_ent[1]=0.f; }
  if (idx >= 32*64*32) return;
  int lane=idx&31, np=(idx>>5)&63, kc=idx>>11;
  int k0=(kc<<4)+((lane&3)<<1);
  uint4 b;
  #pragma unroll
  for (int s=0;s<2;s++){
    int n8=(np<<1)+s;
    int n=(n8<<3)+(lane>>2), grow=(n&3)*256+(n>>2);
    unsigned fx = pk2f(wval(k0  ,grow,Wih,Whh), wval(k0+1,grow,Wih,Whh));
    unsigned fy = pk2f(wval(k0+8,grow,Wih,Whh), wval(k0+9,grow,Wih,Whh));
    if (s==0){ b.x=fx; b.y=fy; } else { b.z=fx; b.w=fy; }
  }
  g_Bp[idx]=b;
}

__global__ void prep_g4(const float* Wih,const float* bi,const float* bh,
                        const float* ae,const float* be,const float* ie){
  int idx=blockIdx.x*blockDim.x+threadIdx.x;
  if (idx>=4*16*1024) return;
  int col=idx&1023, prev=(idx>>10)&15, sel=idx>>14;
  int grow=(col&3)*256+(col>>2);
  int br=sel>>1, ad=sel&1;
  float s=bi[grow]+bh[grow];
  for(int e=0;e<64;e++) s+=Wih[grow*448+256+e]*be[br*64+e];
  for(int e=0;e<64;e++) s+=Wih[grow*448+320+e]*ie[ad*64+e];
  for(int e=0;e<64;e++) s+=Wih[grow*448+384+e]*ae[prev*64+e];
  g_G4[idx]=s;
}

// 16 k-chunks of MMA starting at A column kb0, B chunk index kcb
__device__ __forceinline__ void mma16(float (&acc)[8][2][4], unsigned abase,int kb0,int kcb,
                                      int mtb,int rowA,int kadj,int n8b,int lane){
  #pragma unroll 2
  for (int kc=0;kc<16;kc++){
    int kb=kb0+(kc<<4);
    unsigned a0[2],a1[2],a2[2],a3[2];
    #pragma unroll
    for (int m=0;m<2;m++){
      unsigned aa = abase + (unsigned)(((((mtb+m)<<4)+rowA)*ASTR + kb + kadj)<<1);
      LDSM4(a0[m],a1[m],a2[m],a3[m],aa);
    }
    const uint4* bp = g_Bp + ((size_t)(((kcb+kc)<<6))+(n8b>>1))*32 + lane;
    #pragma unroll
    for (int jp=0;jp<4;jp++){
      uint4 b = bp[jp<<5];
      #pragma unroll
      for (int m=0;m<2;m++){
        MMA(acc[2*jp  ][m], a0[m],a1[m],a2[m],a3[m], b.x, b.y);
        MMA(acc[2*jp+1][m], a0[m],a1[m],a2[m],a3[m], b.z, b.w);
      }
    }
  }
}

__device__ __forceinline__ void epilogue(float (&acc)[8][2][4], float* creg, int pass,
                                         ush* A, int hout, int sel, const int* s_pidx,
                                         int mtb, int lane, int n8b){
  #pragma unroll
  for (int j=0;j<8;j++){
    int n8=n8b+j;
    #pragma unroll
    for (int m=0;m<2;m++){
      float c0=acc[j][m][0],c1=acc[j][m][1],c2=acc[j][m][2],c3=acc[j][m][3];
      float t0=__shfl_xor_sync(~0u,c0,1), t1=__shfl_xor_sync(~0u,c1,1);
      float t2=__shfl_xor_sync(~0u,c2,1), t3=__shfl_xor_sync(~0u,c3,1);
      float gi_,gf_,gg_,go_; int row;
      if (lane&1){ gi_=t2; gf_=t3; gg_=c2; go_=c3; row=((mtb+m)<<4)+(lane>>2)+8; }
      else       { gi_=c0; gf_=c1; gg_=t0; go_=t1; row=((mtb+m)<<4)+(lane>>2); }
      int u=(n8<<1)|((lane>>1)&1);
      int prev=s_pidx[row];
      const float4 tv = *(const float4*)(g_G4 + (((sel<<4)+prev)<<10) + (u<<2));
      gi_+=tv.x; gf_+=tv.y; gg_+=tv.z; go_+=tv.w;
      float cr = creg[(pass<<4)|(j<<1)|m];
      float cn = sigf(gf_)*cr + sigf(gi_)*tanha(gg_);
      creg[(pass<<4)|(j<<1)|m]=cn;
      A[row*ASTR+hout+u]=f2b(sigf(go_)*tanha(cn));
    }
  }
}

__device__ __forceinline__ void do_heads(int hp,int hoff, ush* A,
    const int* t_act,const int* m_act,const float* Wt,const float* bt,
    const float* Wm,const float* bm,int* s_pidx,int* s_mask,float* s_lp,
    int r0,int wid,int lane,float& eT,float& eM){
  const int branch=hp>>3, isM=hp&1, step=(hp>>1)&3;
  for (int rr=0;rr<4;rr++){
    int r=(wid<<2)+rr;
    const ush* hr = A + r*ASTR + hoff;
    if (!isM){
      float a0=0.f,a1=0.f,a2=0.f,a3=0.f;
      #pragma unroll
      for (int kk=0;kk<8;kk++){
        int k=lane+(kk<<5); float hv=b2f(hr[k]);
        a0+=Wt[k]*hv; a1+=Wt[256+k]*hv; a2+=Wt[512+k]*hv; a3+=Wt[768+k]*hv;
      }
      #pragma unroll
      for (int o=16;o;o>>=1){
        a0+=__shfl_xor_sync(~0u,a0,o); a1+=__shfl_xor_sync(~0u,a1,o);
        a2+=__shfl_xor_sync(~0u,a2,o); a3+=__shfl_xor_sync(~0u,a3,o);
      }
      int mk=s_mask[r];
      float l0=(mk&1)?a0+bt[0]:NEGBIG, l1=(mk&2)?a1+bt[1]:NEGBIG;
      float l2=(mk&4)?a2+bt[2]:NEGBIG, l3=(mk&8)?a3+bt[3]:NEGBIG;
      float mx=fmaxf(fmaxf(l0,l1),fmaxf(l2,l3));
      float e0=__expf(l0-mx),e1=__expf(l1-mx),e2=__expf(l2-mx),e3=__expf(l3-mx);
      float se=e0+e1+e2+e3, sl=e0*l0+e1*l1+e2*l2+e3*l3, lse=mx+__logf(se);
      int ta=t_act[(size_t)(r0+r)*8+branch*4+step];
      float lsel=(ta==0)?l0:(ta==1)?l1:(ta==2)?l2:l3;
      if (lane==0){
        s_lp[r]+=lsel-lse; s_mask[r]=mk&~(1<<ta); eT+=lse-sl/se;
        s_pidx[r]=ta;
      }
    } else {
      float a[NMM];
      #pragma unroll
      for (int j=0;j<NMM;j++) a[j]=0.f;
      #pragma unroll
      for (int kk=0;kk<8;kk++){
        int k=lane+(kk<<5); float hv=b2f(hr[k]);
        #pragma unroll
        for (int j=0;j<NMM;j++) a[j]+=Wm[j*256+k]*hv;
      }
      #pragma unroll
      for (int j=0;j<NMM;j++)
        #pragma unroll
        for (int o=16;o;o>>=1) a[j]+=__shfl_xor_sync(~0u,a[j],o);
      float mx=-1e30f;
      #pragma unroll
      for (int j=0;j<NMM;j++){ a[j]+=bm[j]; mx=fmaxf(mx,a[j]); }
      float se=0.f,sl=0.f;
      #pragma unroll
      for (int j=0;j<NMM;j++){ float e=__expf(a[j]-mx); se+=e; sl+=e*a[j]; }
      float lse=mx+__logf(se);
      int ma=m_act[(size_t)(r0+r)*8+branch*4+step];
      float lsel=a[0];
      #pragma unroll
      for (int j=1;j<NMM;j++) lsel=(j==ma)?a[j]:lsel;
      if (lane==0){
        s_lp[r]+=lsel-lse; eM+=lse-sl/se;
        s_pidx[r]=ma;
      }
    }
  }
}

__global__ void __launch_bounds__(NTH,1) decoder_kernel(
  const float* __restrict__ z1, const float* __restrict__ z2,
  const int* __restrict__ t_act, const int* __restrict__ m_act,
  const float* __restrict__ Wt, const float* __restrict__ bt,
  const float* __restrict__ Wm, const float* __restrict__ bm,
  float* __restrict__ out)
{
  extern __shared__ ush A[];
  __shared__ int   s_pidx[RB], s_mask[RB];
  __shared__ float s_lp[RB], s_red[32];

  const int t=threadIdx.x, wid=t>>5, lane=t&31;
  const int r0=blockIdx.x*RB;
  const unsigned abase=su32(A);
  const int rowA=lane&15, kadj=(lane>>4)<<3;
  const int mtb=(wid>>3)<<1;
  const int n8w=(wid&7)<<3;
  float eT=0.f, eM=0.f;
  float creg[32];
  #pragma unroll
  for (int i=0;i<32;i++) creg[i]=0.f;

  for (int i=t;i<RB*ASTR;i+=NTH) A[i]=0;
  for (int i=t;i<RB*256;i+=NTH)
    A[(i>>8)*ASTR+(i&255)] = f2b(z1[(size_t)(r0+(i>>8))*256+(i&255)]);
  if (t<RB){ s_pidx[t]=15; s_mask[t]=15; s_lp[t]=0.f; }

  for (int ss=0; ss<16; ss++){
    const int hin=256+((ss&1)<<8), hout=256+((1-(ss&1))<<8);
    const bool bstart=(ss==0)||(ss==8);
    const int sel=((ss>>3)<<1)|(ss&1);
    __syncthreads();

    float acc[8][2][4];
    // ---- pass 0 MMA (no dependence on heads of ss-1) ----
    {
      uint4* wzp = g_wz4 + ((size_t)(blockIdx.x*2+0)*8)*512 + t;
      if (bstart){
        #pragma unroll
        for (int j=0;j<8;j++)
          #pragma unroll
          for (int m=0;m<2;m++){ acc[j][m][0]=0.f; acc[j][m][1]=0.f; acc[j][m][2]=0.f; acc[j][m][3]=0.f; }
        mma16(acc,abase,0,0,mtb,rowA,kadj,n8w,lane);
        #pragma unroll
        for (int j=0;j<8;j++){
          uint4 s;
          s.x=pk2f(acc[j][0][0],acc[j][0][1]); s.y=pk2f(acc[j][0][2],acc[j][0][3]);
          s.z=pk2f(acc[j][1][0],acc[j][1][1]); s.w=pk2f(acc[j][1][2],acc[j][1][3]);
          wzp[(size_t)j*512]=s;
        }
        if (ss==8) mma16(acc,abase,hin,16,mtb,rowA,kadj,n8w,lane);
      } else {
        #pragma unroll
        for (int j=0;j<8;j++){
          uint4 s = wzp[(size_t)j*512];
          acc[j][0][0]=xlo(s.x); acc[j][0][1]=xhi(s.x);
          acc[j][0][2]=xlo(s.y); acc[j][0][3]=xhi(s.y);
          acc[j][1][0]=xlo(s.z); acc[j][1][1]=xhi(s.z);
          acc[j][1][2]=xlo(s.w); acc[j][1][3]=xhi(s.w);
        }
        mma16(acc,abase,hin,16,mtb,rowA,kadj,n8w,lane);
      }
    }
    // ---- heads for substep ss-1 (overlaps other warps' MMA) ----
    if (ss>0)
      do_heads(ss-1,hin,A,t_act,m_act,Wt,bt,Wm,bm,s_pidx,s_mask,s_lp,r0,wid,lane,eT,eM);
    if (ss==8 && t<RB) s_mask[t]=15;
    __syncthreads();
    // ---- pass 0 epilogue (needs s_pidx from heads) ----
    epilogue(acc,creg,0,A,hout,sel,s_pidx,mtb,lane,n8w);
    // ---- pass 1 ----
    {
      const int n8b=64+n8w;
      uint4* wzp = g_wz4 + ((size_t)(blockIdx.x*2+1)*8)*512 + t;
      if (bstart){
        #pragma unroll
        for (int j=0;j<8;j++)
          #pragma unroll
          for (int m=0;m<2;m++){ acc[j][m][0]=0.f; acc[j][m][1]=0.f; acc[j][m][2]=0.f; acc[j][m][3]=0.f; }
        mma16(acc,abase,0,0,mtb,rowA,kadj,n8b,lane);
        #pragma unroll
        for (int j=0;j<8;j++){
          uint4 s;
          s.x=pk2f(acc[j][0][0],acc[j][0][1]); s.y=pk2f(acc[j][0][2],acc[j][0][3]);
          s.z=pk2f(acc[j][1][0],acc[j][1][1]); s.w=pk2f(acc[j][1][2],acc[j][1][3]);
          wzp[(size_t)j*512]=s;
        }
        if (ss==8) mma16(acc,abase,hin,16,mtb,rowA,kadj,n8b,lane);
      } else {
        #pragma unroll
        for (int j=0;j<8;j++){
          uint4 s = wzp[(size_t)j*512];
          acc[j][0][0]=xlo(s.x); acc[j][0][1]=xhi(s.x);
          acc[j][0][2]=xlo(s.y); acc[j][0][3]=xhi(s.y);
          acc[j][1][0]=xlo(s.z); acc[j][1][1]=xhi(s.z);
          acc[j][1][2]=xlo(s.w); acc[j][1][3]=xhi(s.w);
        }
        mma16(acc,abase,hin,16,mtb,rowA,kadj,n8b,lane);
      }
      epilogue(acc,creg,1,A,hout,sel,s_pidx,mtb,lane,n8b);
    }
    if (ss==7){
      for (int i=t;i<RB*256;i+=NTH)
        A[(i>>8)*ASTR+(i&255)] = f2b(z2[(size_t)(r0+(i>>8))*256+(i&255)]);
    }
  }

  __syncthreads();
  do_heads(15,256,A,t_act,m_act,Wt,bt,Wm,bm,s_pidx,s_mask,s_lp,r0,wid,lane,eT,eM);

  __syncthreads();
  if (t<RB) out[r0+t]=s_lp[t];
  if (lane==0){ s_red[wid]=eT; s_red[16+wid]=eM; }
  __syncthreads();
  if (t==0){
    float sT=0.f,sM=0.f;
    for (int w=0;w<16;w++){ sT+=s_red[w]; sM+=s_red[16+w]; }
    atomicAdd(&g_ent[0],sT); atomicAdd(&g_ent[1],sM);
  }
}

__global__ void finalize_kernel(float* out,int off){
  if (threadIdx.x==0 && blockIdx.x==0){
    const float sc=1.0f/(65536.0f*8.0f);
    out[off]=g_ent[0]*sc; out[off+1]=g_ent[1]*sc;
  }
}
__global__ void cvt_kernel(const int* ti,const int* mi,float* out){
  int i=blockIdx.x*blockDim.x+threadIdx.x;
  if (i<65536*8){ out[65536+i]=(float)ti[i]; out[65536+65536*8+i]=(float)mi[i]; }
}

extern "C" void kernel_launch(void* const* d_in, const int* in_sizes, int n_in,
                              void* d_out, int out_size)
{
  (void)in_sizes; (void)n_in;
  const float* z1=(const float*)d_in[0];  const float* z2=(const float*)d_in[1];
  const int* t_act=(const int*)d_in[2];   const int* m_act=(const int*)d_in[3];
  const float* aemb=(const float*)d_in[4];const float* bemb=(const float*)d_in[5];
  const float* idemb=(const float*)d_in[6];
  const float* Wih=(const float*)d_in[7]; const float* Whh=(const float*)d_in[8];
  const float* bih=(const float*)d_in[9]; const float* bhh=(const float*)d_in[10];
  const float* Wt=(const float*)d_in[11]; const float* bt=(const float*)d_in[12];
  const float* Wm=(const float*)d_in[13]; const float* bm=(const float*)d_in[14];
  float* out=(float*)d_out;

  const int SMEM = RB*ASTR*2;
  cudaFuncSetAttribute(decoder_kernel, cudaFuncAttributeMaxDynamicSharedMemorySize, SMEM);

  prep_bfrag<<<(32*64*32+255)/256,256>>>(Wih,Whh);
  prep_g4<<<(4*16*1024+255)/256,256>>>(Wih,bih,bhh,aemb,bemb,idemb);
  decoder_kernel<<<65536/RB, NTH, SMEM>>>(z1,z2,t_act,m_act,Wt,bt,Wm,bm,out);

  const int NACT=65536*8;
  if (out_size >= 65536+2*NACT+2){
    cvt_kernel<<<(NACT+255)/256,256>>>(t_act,m_act,out);
    finalize_kernel<<<1,32>>>(out,65536+2*NACT);
  } else if (out_size >= 65536+2){
    finalize_kernel<<<1,32>>>(out,65536);
  }
}

// round 15
// speedup vs baseline: 1.2023x; 1.2023x over previous
#include <cuda_runtime.h>
#include <cuda_bf16.h>
typedef unsigned short ush;

#define RB   64
#define NTH  512
#define ASTR 808
#define CSTR 258
#define NMM  11
#define NEGBIG -1000000000.0f

__device__ uint4 g_Bp[32*64*32];        // [kc][n8pair][lane] packed b-fragments (z+h only)
__device__ uint4 g_wz4[1024*2*8*512];   // per-CTA z-GEMM partial (bf16-packed acc)
__device__ float g_G4[4*16*1024];       // [sel][prev][col] f32 gate-bias table
__device__ float g_ent[2];

__device__ __forceinline__ unsigned su32(const void* p){
  unsigned r; asm("{.reg .u64 t; cvta.to.shared.u64 t, %1; cvt.u32.u64 %0, t;}" : "=r"(r) : "l"(p)); return r; }
__device__ __forceinline__ ush f2b(float x){ return __bfloat16_as_ushort(__float2bfloat16_rn(x)); }
__device__ __forceinline__ float b2f(ush u){ return __bfloat162float(__ushort_as_bfloat16(u)); }
__device__ __forceinline__ float tanha(float x){ float y; asm("tanh.approx.f32 %0, %1;" : "=f"(y) : "f"(x)); return y; }
__device__ __forceinline__ float sigf(float x){ return fmaf(0.5f, tanha(0.5f*x), 0.5f); }
__device__ __forceinline__ unsigned pk2f(float lo,float hi){
  return (unsigned)__bfloat16_as_ushort(__float2bfloat16_rn(lo)) |
         ((unsigned)__bfloat16_as_ushort(__float2bfloat16_rn(hi))<<16); }
__device__ __forceinline__ float xlo(unsigned u){ return __uint_as_float(u<<16); }
__device__ __forceinline__ float xhi(unsigned u){ return __uint_as_float(u & 0xffff0000u); }

#define LDSM4(r0,r1,r2,r3,a) asm volatile( \
  "ldmatrix.sync.aligned.m8n8.x4.shared.b16 {%0,%1,%2,%3},[%4];" \
  : "=r"(r0),"=r"(r1),"=r"(r2),"=r"(r3) : "r"(a))
#define MMA(d,a0,a1,a2,a3,b0,b1) asm( \
  "mma.sync.aligned.m16n8k16.row.col.f32.bf16.bf16.f32 {%0,%1,%2,%3},{%4,%5,%6,%7},{%8,%9},{%0,%1,%2,%3};" \
  : "+f"(d[0]),"+f"(d[1]),"+f"(d[2]),"+f"(d[3]) : "r"(a0),"r"(a1),"r"(a2),"r"(a3),"r"(b0),"r"(b1))

// B' rows: k<256 Wz, k<512 Whh. col=4*unit+gate.
__device__ float wval(int k,int grow,const float* Wih,const float* Whh){
  if (k<256) return Wih[grow*448+k];
  if (k<512) return Whh[grow*256+(k-256)];
  return 0.f;
}

__global__ void prep_bfrag(const float* Wih,const float* Whh){
  int idx = blockIdx.x*blockDim.x + threadIdx.x;
  if (idx==0){ g_ent[0]=0.f; g_ent[1]=0.f; }
  if (idx >= 32*64*32) return;
  int lane=idx&31, np=(idx>>5)&63, kc=idx>>11;
  int k0=(kc<<4)+((lane&3)<<1);
  uint4 b;
  #pragma unroll
  for (int s=0;s<2;s++){
    int n8=(np<<1)+s;
    int n=(n8<<3)+(lane>>2), grow=(n&3)*256+(n>>2);
    unsigned fx = pk2f(wval(k0  ,grow,Wih,Whh), wval(k0+1,grow,Wih,Whh));
    unsigned fy = pk2f(wval(k0+8,grow,Wih,Whh), wval(k0+9,grow,Wih,Whh));
    if (s==0){ b.x=fx; b.y=fy; } else { b.z=fx; b.w=fy; }
  }
  g_Bp[idx]=b;
}

__global__ void prep_g4(const float* Wih,const float* bi,const float* bh,
                        const float* ae,const float* be,const float* ie){
  int idx=blockIdx.x*blockDim.x+threadIdx.x;
  if (idx>=4*16*1024) return;
  int col=idx&1023, prev=(idx>>10)&15, sel=idx>>14;
  int grow=(col&3)*256+(col>>2);
  int br=sel>>1, ad=sel&1;
  float s=bi[grow]+bh[grow];
  for(int e=0;e<64;e++) s+=Wih[grow*448+256+e]*be[br*64+e];
  for(int e=0;e<64;e++) s+=Wih[grow*448+320+e]*ie[ad*64+e];
  for(int e=0;e<64;e++) s+=Wih[grow*448+384+e]*ae[prev*64+e];
  g_G4[idx]=s;
}

__global__ void __launch_bounds__(NTH,1) decoder_kernel(
  const float* __restrict__ z1, const float* __restrict__ z2,
  const int* __restrict__ t_act, const int* __restrict__ m_act,
  const float* __restrict__ Wt, const float* __restrict__ bt,
  const float* __restrict__ Wm, const float* __restrict__ bm,
  float* __restrict__ out)
{
  extern __shared__ ush A[];                 // [64][ASTR] bf16
  float* Csm = (float*)(A + RB*ASTR);        // [64][CSTR] f32
  __shared__ int   s_pidx[RB], s_mask[RB];
  __shared__ float s_lp[RB], s_red[32];

  const int t=threadIdx.x, wid=t>>5, lane=t&31;
  const int r0=blockIdx.x*RB;
  const unsigned abase=su32(A);
  const int rowA=lane&15, kadj=(lane>>4)<<3;
  const int mtb=(wid>>3)<<1;
  const int n8w=(wid&7)<<3;
  float eT=0.f, eM=0.f;

  for (int i=t;i<RB*ASTR;i+=NTH) A[i]=0;
  for (int i=t;i<RB*CSTR;i+=NTH) Csm[i]=0.f;
  for (int i=t;i<RB*256;i+=NTH)
    A[(i>>8)*ASTR+(i&255)] = f2b(z1[(size_t)(r0+(i>>8))*256+(i&255)]);
  if (t<RB){ s_pidx[t]=15; s_mask[t]=15; s_lp[t]=0.f; }

  for (int ss=0; ss<16; ss++){
    const int hin = 256+((ss&1)<<8), hout = 256+((1-(ss&1))<<8);
    const bool bstart = (ss==0)||(ss==8);
    const int sel=((ss>>3)<<1)|(ss&1);
    __syncthreads();
    #pragma unroll 1
    for (int pass=0; pass<2; pass++){
      const int n8b = (pass<<6)+n8w;
      uint4* wzp = g_wz4 + ((size_t)(blockIdx.x*2+pass)*8)*512 + t;
      float acc[8][2][4];
      if (bstart){
        #pragma unroll
        for (int j=0;j<8;j++)
          #pragma unroll
          for (int m=0;m<2;m++){ acc[j][m][0]=0.f; acc[j][m][1]=0.f; acc[j][m][2]=0.f; acc[j][m][3]=0.f; }
        // z chunks
        #pragma unroll 2
        for (int kc=0;kc<16;kc++){
          int kb = kc<<4;
          unsigned a0[2],a1[2],a2[2],a3[2];
          #pragma unroll
          for (int m=0;m<2;m++){
            unsigned aa = abase + (unsigned)(((((mtb+m)<<4)+rowA)*ASTR + kb + kadj)<<1);
            LDSM4(a0[m],a1[m],a2[m],a3[m],aa);
          }
          const uint4* bp = g_Bp + ((size_t)(kc<<6)+(n8b>>1))*32 + lane;
          #pragma unroll
          for (int jp=0;jp<4;jp++){
            uint4 b = bp[jp<<5];
            #pragma unroll
            for (int m=0;m<2;m++){
              MMA(acc[2*jp  ][m], a0[m],a1[m],a2[m],a3[m], b.x, b.y);
              MMA(acc[2*jp+1][m], a0[m],a1[m],a2[m],a3[m], b.z, b.w);
            }
          }
        }
        // snapshot z-partial (bf16)
        #pragma unroll
        for (int j=0;j<8;j++){
          uint4 s;
          s.x = pk2f(acc[j][0][0],acc[j][0][1]);
          s.y = pk2f(acc[j][0][2],acc[j][0][3]);
          s.z = pk2f(acc[j][1][0],acc[j][1][1]);
          s.w = pk2f(acc[j][1][2],acc[j][1][3]);
          wzp[(size_t)j*512] = s;
        }
      } else {
        #pragma unroll
        for (int j=0;j<8;j++){
          uint4 s = wzp[(size_t)j*512];
          acc[j][0][0]=xlo(s.x); acc[j][0][1]=xhi(s.x);
          acc[j][0][2]=xlo(s.y); acc[j][0][3]=xhi(s.y);
          acc[j][1][0]=xlo(s.z); acc[j][1][1]=xhi(s.z);
          acc[j][1][2]=xlo(s.w); acc[j][1][3]=xhi(s.w);
        }
      }
      // h chunks (skip at ss==0 where h == 0)
      if (ss>0){
        #pragma unroll 2
        for (int kc=16;kc<32;kc++){
          int kb = hin+((kc-16)<<4);
          unsigned a0[2],a1[2],a2[2],a3[2];
          #pragma unroll
          for (int m=0;m<2;m++){
            unsigned aa = abase + (unsigned)(((((mtb+m)<<4)+rowA)*ASTR + kb + kadj)<<1);
            LDSM4(a0[m],a1[m],a2[m],a3[m],aa);
          }
          const uint4* bp = g_Bp + ((size_t)(kc<<6)+(n8b>>1))*32 + lane;
          #pragma unroll
          for (int jp=0;jp<4;jp++){
            uint4 b = bp[jp<<5];
            #pragma unroll
            for (int m=0;m<2;m++){
              MMA(acc[2*jp  ][m], a0[m],a1[m],a2[m],a3[m], b.x, b.y);
              MMA(acc[2*jp+1][m], a0[m],a1[m],a2[m],a3[m], b.z, b.w);
            }
          }
        }
      }
      // epilogue: add G4[sel][prev] table, LSTM elementwise
      #pragma unroll
      for (int j=0;j<8;j++){
        int n8=n8b+j;
        #pragma unroll
        for (int m=0;m<2;m++){
          float c0=acc[j][m][0],c1=acc[j][m][1],c2=acc[j][m][2],c3=acc[j][m][3];
          float t0=__shfl_xor_sync(~0u,c0,1), t1=__shfl_xor_sync(~0u,c1,1);
          float t2=__shfl_xor_sync(~0u,c2,1), t3=__shfl_xor_sync(~0u,c3,1);
          float gi_,gf_,gg_,go_; int row;
          if (lane&1){ gi_=t2; gf_=t3; gg_=c2; go_=c3; row=((mtb+m)<<4)+(lane>>2)+8; }
          else       { gi_=c0; gf_=c1; gg_=t0; go_=t1; row=((mtb+m)<<4)+(lane>>2); }
          int u=(n8<<1)|((lane>>1)&1);
          const float4 tv = *(const float4*)(g_G4 + (((sel<<4)+s_pidx[row])<<10) + (u<<2));
          gi_+=tv.x; gf_+=tv.y; gg_+=tv.z; go_+=tv.w;
          float cn = sigf(gf_)*Csm[row*CSTR+u] + sigf(gi_)*tanha(gg_);
          Csm[row*CSTR+u]=cn;
          A[row*ASTR+hout+u]=f2b(sigf(go_)*tanha(cn));
        }
      }
    }
    __syncthreads();

    const int branch=ss>>3, isM=ss&1, step=(ss>>1)&3;
    for (int rr=0;rr<4;rr++){
      int r=(wid<<2)+rr;
      const ush* hr = A + r*ASTR + hout;
      if (!isM){
        float a0=0.f,a1=0.f,a2=0.f,a3=0.f;
        #pragma unroll
        for (int kk=0;kk<8;kk++){
          int k=lane+(kk<<5); float hv=b2f(hr[k]);
          a0+=Wt[k]*hv; a1+=Wt[256+k]*hv; a2+=Wt[512+k]*hv; a3+=Wt[768+k]*hv;
        }
        #pragma unroll
        for (int o=16;o;o>>=1){
          a0+=__shfl_xor_sync(~0u,a0,o); a1+=__shfl_xor_sync(~0u,a1,o);
          a2+=__shfl_xor_sync(~0u,a2,o); a3+=__shfl_xor_sync(~0u,a3,o);
        }
        int mk=s_mask[r];
        float l0=(mk&1)?a0+bt[0]:NEGBIG, l1=(mk&2)?a1+bt[1]:NEGBIG;
        float l2=(mk&4)?a2+bt[2]:NEGBIG, l3=(mk&8)?a3+bt[3]:NEGBIG;
        float mx=fmaxf(fmaxf(l0,l1),fmaxf(l2,l3));
        float e0=__expf(l0-mx),e1=__expf(l1-mx),e2=__expf(l2-mx),e3=__expf(l3-mx);
        float se=e0+e1+e2+e3, sl=e0*l0+e1*l1+e2*l2+e3*l3, lse=mx+__logf(se);
        int ta=t_act[(size_t)(r0+r)*8+branch*4+step];
        float lsel=(ta==0)?l0:(ta==1)?l1:(ta==2)?l2:l3;
        if (lane==0){
          s_lp[r]+=lsel-lse; s_mask[r]=mk&~(1<<ta); eT+=lse-sl/se;
          s_pidx[r]=ta;
        }
      } else {
        float a[NMM];
        #pragma unroll
        for (int j=0;j<NMM;j++) a[j]=0.f;
        #pragma unroll
        for (int kk=0;kk<8;kk++){
          int k=lane+(kk<<5); float hv=b2f(hr[k]);
          #pragma unroll
          for (int j=0;j<NMM;j++) a[j]+=Wm[j*256+k]*hv;
        }
        #pragma unroll
        for (int j=0;j<NMM;j++)
          #pragma unroll
          for (int o=16;o;o>>=1) a[j]+=__shfl_xor_sync(~0u,a[j],o);
        float mx=-1e30f;
        #pragma unroll
        for (int j=0;j<NMM;j++){ a[j]+=bm[j]; mx=fmaxf(mx,a[j]); }
        float se=0.f,sl=0.f;
        #pragma unroll
        for (int j=0;j<NMM;j++){ float e=__expf(a[j]-mx); se+=e; sl+=e*a[j]; }
        float lse=mx+__logf(se);
        int ma=m_act[(size_t)(r0+r)*8+branch*4+step];
        float lsel=a[0];
        #pragma unroll
        for (int j=1;j<NMM;j++) lsel=(j==ma)?a[j]:lsel;
        if (lane==0){
          s_lp[r]+=lsel-lse; eM+=lse-sl/se;
          s_pidx[r]=ma;
        }
      }
    }
    if (ss==7){
      for (int i=t;i<RB*256;i+=NTH)
        A[(i>>8)*ASTR+(i&255)] = f2b(z2[(size_t)(r0+(i>>8))*256+(i&255)]);
      if (t<RB) s_mask[t]=15;
    }
  }

  __syncthreads();
  if (t<RB) out[r0+t]=s_lp[t];
  if (lane==0){ s_red[wid]=eT; s_red[16+wid]=eM; }
  __syncthreads();
  if (t==0){
    float sT=0.f,sM=0.f;
    for (int w=0;w<16;w++){ sT+=s_red[w]; sM+=s_red[16+w]; }
    atomicAdd(&g_ent[0],sT); atomicAdd(&g_ent[1],sM);
  }
}

__global__ void finalize_kernel(float* out,int off){
  if (threadIdx.x==0 && blockIdx.x==0){
    const float sc=1.0f/(65536.0f*8.0f);
    out[off]=g_ent[0]*sc; out[off+1]=g_ent[1]*sc;
  }
}
__global__ void cvt_kernel(const int* ti,const int* mi,float* out){
  int i=blockIdx.x*blockDim.x+threadIdx.x;
  if (i<65536*8){ out[65536+i]=(float)ti[i]; out[65536+65536*8+i]=(float)mi[i]; }
}

extern "C" void kernel_launch(void* const* d_in, const int* in_sizes, int n_in,
                              void* d_out, int out_size)
{
  (void)in_sizes; (void)n_in;
  const float* z1=(const float*)d_in[0];  const float* z2=(const float*)d_in[1];
  const int* t_act=(const int*)d_in[2];   const int* m_act=(const int*)d_in[3];
  const float* aemb=(const float*)d_in[4];const float* bemb=(const float*)d_in[5];
  const float* idemb=(const float*)d_in[6];
  const float* Wih=(const float*)d_in[7]; const float* Whh=(const float*)d_in[8];
  const float* bih=(const float*)d_in[9]; const float* bhh=(const float*)d_in[10];
  const float* Wt=(const float*)d_in[11]; const float* bt=(const float*)d_in[12];
  const float* Wm=(const float*)d_in[13]; const float* bm=(const float*)d_in[14];
  float* out=(float*)d_out;

  const int SMEM = RB*ASTR*2 + RB*CSTR*4;
  cudaFuncSetAttribute(decoder_kernel, cudaFuncAttributeMaxDynamicSharedMemorySize, SMEM);

  prep_bfrag<<<(32*64*32+255)/256,256>>>(Wih,Whh);
  prep_g4<<<(4*16*1024+255)/256,256>>>(Wih,bih,bhh,aemb,bemb,idemb);
  decoder_kernel<<<65536/RB, NTH, SMEM>>>(z1,z2,t_act,m_act,Wt,bt,Wm,bm,out);

  const int NACT=65536*8;
  if (out_size >= 65536+2*NACT+2){
    cvt_kernel<<<(NACT+255)/256,256>>>(t_act,m_act,out);
    finalize_kernel<<<1,32>>>(out,65536+2*NACT);
  } else if (out_size >= 65536+2){
    finalize_kernel<<<1,32>>>(out,65536);
  }
}

// round 16
// speedup vs baseline: 1.3215x; 1.0991x over previous
#include <cuda_runtime.h>
#include <cuda_bf16.h>
typedef unsigned short ush;

#define RB   64
#define NTH  512
#define ASTR 808
#define CSTR 258
#define NMM  11
#define NEGBIG -1000000000.0f

__device__ uint4 g_Bp[33*64*32];        // [kc][n8pair][lane]; kc32 = Gp one-hot rows
__device__ uint4 g_wz4[1024*2*8*512];   // per-CTA z-GEMM partial (bf16-packed acc)
__device__ float g_Cb[4*1024];          // [sel][col] f32 bias+branch+aid table
__device__ float g_ent[2];

__device__ __forceinline__ unsigned su32(const void* p){
  unsigned r; asm("{.reg .u64 t; cvta.to.shared.u64 t, %1; cvt.u32.u64 %0, t;}" : "=r"(r) : "l"(p)); return r; }
__device__ __forceinline__ ush f2b(float x){ return __bfloat16_as_ushort(__float2bfloat16_rn(x)); }
__device__ __forceinline__ float b2f(ush u){ return __bfloat162float(__ushort_as_bfloat16(u)); }
__device__ __forceinline__ float tanha(float x){ float y; asm("tanh.approx.f32 %0, %1;" : "=f"(y) : "f"(x)); return y; }
__device__ __forceinline__ float sigf(float x){ return fmaf(0.5f, tanha(0.5f*x), 0.5f); }
__device__ __forceinline__ unsigned pk2f(float lo,float hi){
  return (unsigned)__bfloat16_as_ushort(__float2bfloat16_rn(lo)) |
         ((unsigned)__bfloat16_as_ushort(__float2bfloat16_rn(hi))<<16); }
__device__ __forceinline__ float xlo(unsigned u){ return __uint_as_float(u<<16); }
__device__ __forceinline__ float xhi(unsigned u){ return __uint_as_float(u & 0xffff0000u); }

#define LDSM4(r0,r1,r2,r3,a) asm volatile( \
  "ldmatrix.sync.aligned.m8n8.x4.shared.b16 {%0,%1,%2,%3},[%4];" \
  : "=r"(r0),"=r"(r1),"=r"(r2),"=r"(r3) : "r"(a))
#define MMA(d,a0,a1,a2,a3,b0,b1) asm( \
  "mma.sync.aligned.m16n8k16.row.col.f32.bf16.bf16.f32 {%0,%1,%2,%3},{%4,%5,%6,%7},{%8,%9},{%0,%1,%2,%3};" \
  : "+f"(d[0]),"+f"(d[1]),"+f"(d[2]),"+f"(d[3]) : "r"(a0),"r"(a1),"r"(a2),"r"(a3),"r"(b0),"r"(b1))

// B' rows: k<256 Wz, k<512 Whh, k<528 Gp(prev one-hot). col=4*unit+gate.
__device__ float wval(int k,int grow,const float* Wih,const float* Whh,const float* ae){
  if (k<256) return Wih[grow*448+k];
  if (k<512) return Whh[grow*256+(k-256)];
  if (k<528){ float s=0.f; int p=k-512; for(int e=0;e<64;e++) s+=Wih[grow*448+384+e]*ae[p*64+e]; return s; }
  return 0.f;
}

__global__ void prep_bfrag(const float* Wih,const float* Whh,const float* ae){
  int idx = blockIdx.x*blockDim.x + threadIdx.x;
  if (idx==0){ g_ent[0]=0.f; g_ent[1]=0.f; }
  if (idx >= 33*64*32) return;
  int lane=idx&31, np=(idx>>5)&63, kc=idx>>11;
  int k0=(kc<<4)+((lane&3)<<1);
  uint4 b;
  #pragma unroll
  for (int s=0;s<2;s++){
    int n8=(np<<1)+s;
    int n=(n8<<3)+(lane>>2), grow=(n&3)*256+(n>>2);
    unsigned fx = pk2f(wval(k0  ,grow,Wih,Whh,ae), wval(k0+1,grow,Wih,Whh,ae));
    unsigned fy = pk2f(wval(k0+8,grow,Wih,Whh,ae), wval(k0+9,grow,Wih,Whh,ae));
    if (s==0){ b.x=fx; b.y=fy; } else { b.z=fx; b.w=fy; }
  }
  g_Bp[idx]=b;
}

__global__ void prep_cb(const float* Wih,const float* bi,const float* bh,
                        const float* be,const float* ie){
  int idx=blockIdx.x*blockDim.x+threadIdx.x;
  if (idx>=4*1024) return;
  int col=idx&1023, sel=idx>>10;
  int grow=(col&3)*256+(col>>2);
  int br=sel>>1, ad=sel&1;
  float s=bi[grow]+bh[grow];
  for(int e=0;e<64;e++) s+=Wih[grow*448+256+e]*be[br*64+e];
  for(int e=0;e<64;e++) s+=Wih[grow*448+320+e]*ie[ad*64+e];
  g_Cb[idx]=s;
}

__global__ void __launch_bounds__(NTH,1) decoder_kernel(
  const float* __restrict__ z1, const float* __restrict__ z2,
  const int* __restrict__ t_act, const int* __restrict__ m_act,
  const float* __restrict__ Wt, const float* __restrict__ bt,
  const float* __restrict__ Wm, const float* __restrict__ bm,
  float* __restrict__ out)
{
  extern __shared__ ush A[];                 // [64][ASTR] bf16
  float* Csm = (float*)(A + RB*ASTR);        // [64][CSTR] f32
  float* sCb = Csm + RB*CSTR;                // [1024] f32 staged Cbase row
  __shared__ int   s_pidx[RB], s_mask[RB];
  __shared__ float s_lp[RB], s_red[32];

  const int t=threadIdx.x, wid=t>>5, lane=t&31;
  const int r0=blockIdx.x*RB;
  const unsigned abase=su32(A);
  const int rowA=lane&15, kadj=(lane>>4)<<3;
  const int mtb=(wid>>3)<<1;
  const int n8w=(wid&7)<<3;
  float eT=0.f, eM=0.f;

  for (int i=t;i<RB*ASTR;i+=NTH) A[i]=0;
  for (int i=t;i<RB*CSTR;i+=NTH) Csm[i]=0.f;
  for (int i=t;i<RB*256;i+=NTH)
    A[(i>>8)*ASTR+(i&255)] = f2b(z1[(size_t)(r0+(i>>8))*256+(i&255)]);
  if (t<RB){ s_pidx[t]=15; s_mask[t]=15; s_lp[t]=0.f;
             A[t*ASTR+768+15]=0x3F80; }

  for (int ss=0; ss<16; ss++){
    const int hin = 256+((ss&1)<<8), hout = 256+((1-(ss&1))<<8);
    const bool bstart = (ss==0)||(ss==8);
    const int sel=((ss>>3)<<1)|(ss&1);
    // stage Cbase[sel] (reads of previous value finished before the mid-substep
    // barrier of the prior iteration; top barrier below publishes the new one)
    for (int i=t;i<1024;i+=NTH) sCb[i]=g_Cb[(sel<<10)+i];
    __syncthreads();
    #pragma unroll 1
    for (int pass=0; pass<2; pass++){
      const int n8b = (pass<<6)+n8w;
      uint4* wzp = g_wz4 + ((size_t)(blockIdx.x*2+pass)*8)*512 + t;
      float acc[8][2][4];
      if (bstart){
        #pragma unroll
        for (int j=0;j<8;j++)
          #pragma unroll
          for (int m=0;m<2;m++){ acc[j][m][0]=0.f; acc[j][m][1]=0.f; acc[j][m][2]=0.f; acc[j][m][3]=0.f; }
        // z chunks
        #pragma unroll 2
        for (int kc=0;kc<16;kc++){
          int kb = kc<<4;
          unsigned a0[2],a1[2],a2[2],a3[2];
          #pragma unroll
          for (int m=0;m<2;m++){
            unsigned aa = abase + (unsigned)(((((mtb+m)<<4)+rowA)*ASTR + kb + kadj)<<1);
            LDSM4(a0[m],a1[m],a2[m],a3[m],aa);
          }
          const uint4* bp = g_Bp + ((size_t)(kc<<6)+(n8b>>1))*32 + lane;
          #pragma unroll
          for (int jp=0;jp<4;jp++){
            uint4 b = bp[jp<<5];
            #pragma unroll
            for (int m=0;m<2;m++){
              MMA(acc[2*jp  ][m], a0[m],a1[m],a2[m],a3[m], b.x, b.y);
              MMA(acc[2*jp+1][m], a0[m],a1[m],a2[m],a3[m], b.z, b.w);
            }
          }
        }
        // snapshot z-partial (bf16)
        #pragma unroll
        for (int j=0;j<8;j++){
          uint4 s;
          s.x = pk2f(acc[j][0][0],acc[j][0][1]);
          s.y = pk2f(acc[j][0][2],acc[j][0][3]);
          s.z = pk2f(acc[j][1][0],acc[j][1][1]);
          s.w = pk2f(acc[j][1][2],acc[j][1][3]);
          wzp[(size_t)j*512] = s;
        }
      } else {
        #pragma unroll
        for (int j=0;j<8;j++){
          uint4 s = wzp[(size_t)j*512];
          acc[j][0][0]=xlo(s.x); acc[j][0][1]=xhi(s.x);
          acc[j][0][2]=xlo(s.y); acc[j][0][3]=xhi(s.y);
          acc[j][1][0]=xlo(s.z); acc[j][1][1]=xhi(s.z);
          acc[j][1][2]=xlo(s.w); acc[j][1][3]=xhi(s.w);
        }
      }
      // h chunks (h==0 at ss==0) + prev one-hot chunk (kc32)
      #pragma unroll 1
      for (int kc = (ss>0 ? 16 : 32); kc<33; kc++){
        int kb = kc<32 ? hin+((kc-16)<<4) : 768;
        unsigned a0[2],a1[2],a2[2],a3[2];
        #pragma unroll
        for (int m=0;m<2;m++){
          unsigned aa = abase + (unsigned)(((((mtb+m)<<4)+rowA)*ASTR + kb + kadj)<<1);
          LDSM4(a0[m],a1[m],a2[m],a3[m],aa);
        }
        const uint4* bp = g_Bp + ((size_t)(kc<<6)+(n8b>>1))*32 + lane;
        #pragma unroll
        for (int jp=0;jp<4;jp++){
          uint4 b = bp[jp<<5];
          #pragma unroll
          for (int m=0;m<2;m++){
            MMA(acc[2*jp  ][m], a0[m],a1[m],a2[m],a3[m], b.x, b.y);
            MMA(acc[2*jp+1][m], a0[m],a1[m],a2[m],a3[m], b.z, b.w);
          }
        }
      }
      // epilogue: add staged Cbase[sel] (LDS), LSTM elementwise
      #pragma unroll
      for (int j=0;j<8;j++){
        int n8=n8b+j;
        #pragma unroll
        for (int m=0;m<2;m++){
          float c0=acc[j][m][0],c1=acc[j][m][1],c2=acc[j][m][2],c3=acc[j][m][3];
          float t0=__shfl_xor_sync(~0u,c0,1), t1=__shfl_xor_sync(~0u,c1,1);
          float t2=__shfl_xor_sync(~0u,c2,1), t3=__shfl_xor_sync(~0u,c3,1);
          float gi_,gf_,gg_,go_; int row;
          if (lane&1){ gi_=t2; gf_=t3; gg_=c2; go_=c3; row=((mtb+m)<<4)+(lane>>2)+8; }
          else       { gi_=c0; gf_=c1; gg_=t0; go_=t1; row=((mtb+m)<<4)+(lane>>2); }
          int u=(n8<<1)|((lane>>1)&1);
          const float4 cb = *(const float4*)(sCb + (u<<2));
          gi_+=cb.x; gf_+=cb.y; gg_+=cb.z; go_+=cb.w;
          float cn = sigf(gf_)*Csm[row*CSTR+u] + sigf(gi_)*tanha(gg_);
          Csm[row*CSTR+u]=cn;
          A[row*ASTR+hout+u]=f2b(sigf(go_)*tanha(cn));
        }
      }
    }
    __syncthreads();

    const int branch=ss>>3, isM=ss&1, step=(ss>>1)&3;
    for (int rr=0;rr<4;rr++){
      int r=(wid<<2)+rr;
      const ush* hr = A + r*ASTR + hout;
      if (!isM){
        float a0=0.f,a1=0.f,a2=0.f,a3=0.f;
        #pragma unroll
        for (int kk=0;kk<8;kk++){
          int k=lane+(kk<<5); float hv=b2f(hr[k]);
          a0+=Wt[k]*hv; a1+=Wt[256+k]*hv; a2+=Wt[512+k]*hv; a3+=Wt[768+k]*hv;
        }
        #pragma unroll
        for (int o=16;o;o>>=1){
          a0+=__shfl_xor_sync(~0u,a0,o); a1+=__shfl_xor_sync(~0u,a1,o);
          a2+=__shfl_xor_sync(~0u,a2,o); a3+=__shfl_xor_sync(~0u,a3,o);
        }
        int mk=s_mask[r];
        float l0=(mk&1)?a0+bt[0]:NEGBIG, l1=(mk&2)?a1+bt[1]:NEGBIG;
        float l2=(mk&4)?a2+bt[2]:NEGBIG, l3=(mk&8)?a3+bt[3]:NEGBIG;
        float mx=fmaxf(fmaxf(l0,l1),fmaxf(l2,l3));
        float e0=__expf(l0-mx),e1=__expf(l1-mx),e2=__expf(l2-mx),e3=__expf(l3-mx);
        float se=e0+e1+e2+e3, sl=e0*l0+e1*l1+e2*l2+e3*l3, lse=mx+__logf(se);
        int ta=t_act[(size_t)(r0+r)*8+branch*4+step];
        float lsel=(ta==0)?l0:(ta==1)?l1:(ta==2)?l2:l3;
        if (lane==0){
          s_lp[r]+=lsel-lse; s_mask[r]=mk&~(1<<ta); eT+=lse-sl/se;
          A[r*ASTR+768+s_pidx[r]]=0; A[r*ASTR+768+ta]=0x3F80; s_pidx[r]=ta;
        }
      } else {
        float a[NMM];
        #pragma unroll
        for (int j=0;j<NMM;j++) a[j]=0.f;
        #pragma unroll
        for (int kk=0;kk<8;kk++){
          int k=lane+(kk<<5); float hv=b2f(hr[k]);
          #pragma unroll
          for (int j=0;j<NMM;j++) a[j]+=Wm[j*256+k]*hv;
        }
        #pragma unroll
        for (int j=0;j<NMM;j++)
          #pragma unroll
          for (int o=16;o;o>>=1) a[j]+=__shfl_xor_sync(~0u,a[j],o);
        float mx=-1e30f;
        #pragma unroll
        for (int j=0;j<NMM;j++){ a[j]+=bm[j]; mx=fmaxf(mx,a[j]); }
        float se=0.f,sl=0.f;
        #pragma unroll
        for (int j=0;j<NMM;j++){ float e=__expf(a[j]-mx); se+=e; sl+=e*a[j]; }
        float lse=mx+__logf(se);
        int ma=m_act[(size_t)(r0+r)*8+branch*4+step];
        float lsel=a[0];
        #pragma unroll
        for (int j=1;j<NMM;j++) lsel=(j==ma)?a[j]:lsel;
        if (lane==0){
          s_lp[r]+=lsel-lse; eM+=lse-sl/se;
          A[r*ASTR+768+s_pidx[r]]=0; A[r*ASTR+768+ma]=0x3F80; s_pidx[r]=ma;
        }
      }
    }
    if (ss==7){
      for (int i=t;i<RB*256;i+=NTH)
        A[(i>>8)*ASTR+(i&255)] = f2b(z2[(size_t)(r0+(i>>8))*256+(i&255)]);
      if (t<RB) s_mask[t]=15;
    }
  }

  __syncthreads();
  if (t<RB) out[r0+t]=s_lp[t];
  if (lane==0){ s_red[wid]=eT; s_red[16+wid]=eM; }
  __syncthreads();
  if (t==0){
    float sT=0.f,sM=0.f;
    for (int w=0;w<16;w++){ sT+=s_red[w]; sM+=s_red[16+w]; }
    atomicAdd(&g_ent[0],sT); atomicAdd(&g_ent[1],sM);
  }
}

__global__ void finalize_kernel(float* out,int off){
  if (threadIdx.x==0 && blockIdx.x==0){
    const float sc=1.0f/(65536.0f*8.0f);
    out[off]=g_ent[0]*sc; out[off+1]=g_ent[1]*sc;
  }
}
__global__ void cvt_kernel(const int* ti,const int* mi,float* out){
  int i=blockIdx.x*blockDim.x+threadIdx.x;
  if (i<65536*8){ out[65536+i]=(float)ti[i]; out[65536+65536*8+i]=(float)mi[i]; }
}

extern "C" void kernel_launch(void* const* d_in, const int* in_sizes, int n_in,
                              void* d_out, int out_size)
{
  (void)in_sizes; (void)n_in;
  const float* z1=(const float*)d_in[0];  const float* z2=(const float*)d_in[1];
  const int* t_act=(const int*)d_in[2];   const int* m_act=(const int*)d_in[3];
  const float* aemb=(const float*)d_in[4];const float* bemb=(const float*)d_in[5];
  const float* idemb=(const float*)d_in[6];
  const float* Wih=(const float*)d_in[7]; const float* Whh=(const float*)d_in[8];
  const float* bih=(const float*)d_in[9]; const float* bhh=(const float*)d_in[10];
  const float* Wt=(const float*)d_in[11]; const float* bt=(const float*)d_in[12];
  const float* Wm=(const float*)d_in[13]; const float* bm=(const float*)d_in[14];
  float* out=(float*)d_out;

  const int SMEM = RB*ASTR*2 + RB*CSTR*4 + 1024*4;
  cudaFuncSetAttribute(decoder_kernel, cudaFuncAttributeMaxDynamicSharedMemorySize, SMEM);

  prep_bfrag<<<(33*64*32+255)/256,256>>>(Wih,Whh,aemb);
  prep_cb<<<(4*1024+255)/256,256>>>(Wih,bih,bhh,bemb,idemb);
  decoder_kernel<<<65536/RB, NTH, SMEM>>>(z1,z2,t_act,m_act,Wt,bt,Wm,bm,out);

  const int NACT=65536*8;
  if (out_size >= 65536+2*NACT+2){
    cvt_kernel<<<(NACT+255)/256,256>>>(t_act,m_act,out);
    finalize_kernel<<<1,32>>>(out,65536+2*NACT);
  } else if (out_size >= 65536+2){
    finalize_kernel<<<1,32>>>(out,65536);
  }
}

// round 17
// speedup vs baseline: 1.4521x; 1.0989x over previous
#include <cuda_runtime.h>
#include <cuda_bf16.h>
typedef unsigned short ush;

#define RB   32
#define NTH  256
#define ASTR 808
#define CSTR 258
#define KC   34
#define NMM  11
#define NEGBIG -1000000000.0f

__device__ uint4 g_Bp[KC*64*32];        // [kc][n8pair][lane] packed b-fragments
__device__ uint4 g_wz4[2048*2*8*256];   // per-CTA z-GEMM partial (bf16-packed acc)
__device__ float g_ent[2];

__device__ __forceinline__ unsigned su32(const void* p){
  unsigned r; asm("{.reg .u64 t; cvta.to.shared.u64 t, %1; cvt.u32.u64 %0, t;}" : "=r"(r) : "l"(p)); return r; }
__device__ __forceinline__ ush f2b(float x){ return __bfloat16_as_ushort(__float2bfloat16_rn(x)); }
__device__ __forceinline__ float b2f(ush u){ return __bfloat162float(__ushort_as_bfloat16(u)); }
__device__ __forceinline__ float tanha(float x){ float y; asm("tanh.approx.f32 %0, %1;" : "=f"(y) : "f"(x)); return y; }
__device__ __forceinline__ float sigf(float x){ return fmaf(0.5f, tanha(0.5f*x), 0.5f); }
__device__ __forceinline__ unsigned pk2f(float lo,float hi){
  return (unsigned)__bfloat16_as_ushort(__float2bfloat16_rn(lo)) |
         ((unsigned)__bfloat16_as_ushort(__float2bfloat16_rn(hi))<<16); }
__device__ __forceinline__ float xlo(unsigned u){ return __uint_as_float(u<<16); }
__device__ __forceinline__ float xhi(unsigned u){ return __uint_as_float(u & 0xffff0000u); }

#define LDSM4(r0,r1,r2,r3,a) asm volatile( \
  "ldmatrix.sync.aligned.m8n8.x4.shared.b16 {%0,%1,%2,%3},[%4];" \
  : "=r"(r0),"=r"(r1),"=r"(r2),"=r"(r3) : "r"(a))
#define MMA(d,a0,a1,a2,a3,b0,b1) asm( \
  "mma.sync.aligned.m16n8k16.row.col.f32.bf16.bf16.f32 {%0,%1,%2,%3},{%4,%5,%6,%7},{%8,%9},{%0,%1,%2,%3};" \
  : "+f"(d[0]),"+f"(d[1]),"+f"(d[2]),"+f"(d[3]) : "r"(a0),"r"(a1),"r"(a2),"r"(a3),"r"(b0),"r"(b1))

// B' rows: k<256 Wz, k<512 Whh, k<528 Gp, k<532 Cbase, else 0. col=4*unit+gate.
__device__ float wval(int k,int grow,const float* Wih,const float* Whh,const float* ae,
                      const float* be,const float* ie,const float* bi,const float* bh){
  if (k<256) return Wih[grow*448+k];
  if (k<512) return Whh[grow*256+(k-256)];
  if (k<528){ float s=0.f; int p=k-512; for(int e=0;e<64;e++) s+=Wih[grow*448+384+e]*ae[p*64+e]; return s; }
  if (k<532){ int s4=k-528,br=s4>>1,ad=s4&1; float s=bi[grow]+bh[grow];
    for(int e=0;e<64;e++) s+=Wih[grow*448+256+e]*be[br*64+e];
    for(int e=0;e<64;e++) s+=Wih[grow*448+320+e]*ie[ad*64+e]; return s; }
  return 0.f;
}

__global__ void prep_bfrag(const float* Wih,const float* Whh,const float* ae,
                           const float* be,const float* ie,const float* bi,const float* bh){
  int idx = blockIdx.x*blockDim.x + threadIdx.x;
  if (idx==0){ g_ent[0]=0.f; g_ent[1]=0.f; }
  if (idx >= KC*64*32) return;
  int lane=idx&31, np=(idx>>5)&63, kc=idx>>11;
  int k0=(kc<<4)+((lane&3)<<1);
  uint4 b;
  #pragma unroll
  for (int s=0;s<2;s++){
    int n8=(np<<1)+s;
    int n=(n8<<3)+(lane>>2), grow=(n&3)*256+(n>>2);
    unsigned fx = pk2f(wval(k0  ,grow,Wih,Whh,ae,be,ie,bi,bh), wval(k0+1,grow,Wih,Whh,ae,be,ie,bi,bh));
    unsigned fy = pk2f(wval(k0+8,grow,Wih,Whh,ae,be,ie,bi,bh), wval(k0+9,grow,Wih,Whh,ae,be,ie,bi,bh));
    if (s==0){ b.x=fx; b.y=fy; } else { b.z=fx; b.w=fy; }
  }
  g_Bp[idx]=b;
}

__device__ __forceinline__ void mma_chunk(float (&acc)[8][2][4], unsigned abase, int kb, int kc,
                                          int rowA, int kadj, int n8b, int lane){
  unsigned a0[2],a1[2],a2[2],a3[2];
  #pragma unroll
  for (int m=0;m<2;m++){
    unsigned aa = abase + (unsigned)((((m<<4)+rowA)*ASTR + kb + kadj)<<1);
    LDSM4(a0[m],a1[m],a2[m],a3[m],aa);
  }
  const uint4* bp = g_Bp + ((size_t)(kc<<6)+(n8b>>1))*32 + lane;
  #pragma unroll
  for (int jp=0;jp<4;jp++){
    uint4 b = bp[jp<<5];
    #pragma unroll
    for (int m=0;m<2;m++){
      MMA(acc[2*jp  ][m], a0[m],a1[m],a2[m],a3[m], b.x, b.y);
      MMA(acc[2*jp+1][m], a0[m],a1[m],a2[m],a3[m], b.z, b.w);
    }
  }
}

__global__ void __launch_bounds__(NTH,2) decoder_kernel(
  const float* __restrict__ z1, const float* __restrict__ z2,
  const int* __restrict__ t_act, const int* __restrict__ m_act,
  const float* __restrict__ Wt, const float* __restrict__ bt,
  const float* __restrict__ Wm, const float* __restrict__ bm,
  float* __restrict__ out)
{
  extern __shared__ ush A[];                 // [32][ASTR] bf16
  float* Csm = (float*)(A + RB*ASTR);        // [32][CSTR] f32
  __shared__ int   s_pidx[RB], s_mask[RB];
  __shared__ float s_lp[RB], s_red[16];

  const int t=threadIdx.x, wid=t>>5, lane=t&31;
  const int r0=blockIdx.x*RB;
  const unsigned abase=su32(A);
  const int rowA=lane&15, kadj=(lane>>4)<<3;
  const int n8w=wid<<3;
  float eT=0.f, eM=0.f;

  for (int i=t;i<RB*ASTR;i+=NTH) A[i]=0;
  for (int i=t;i<RB*CSTR;i+=NTH) Csm[i]=0.f;
  for (int i=t;i<RB*256;i+=NTH)
    A[(i>>8)*ASTR+(i&255)] = f2b(z1[(size_t)(r0+(i>>8))*256+(i&255)]);
  if (t<RB){ s_pidx[t]=15; s_mask[t]=15; s_lp[t]=0.f;
             A[t*ASTR+768+15]=0x3F80; A[t*ASTR+784]=0x3F80; }

  for (int ss=0; ss<16; ss++){
    const int hin = 256+((ss&1)<<8), hout = 256+((1-(ss&1))<<8);
    const bool bstart = (ss==0)||(ss==8);
    __syncthreads();
    #pragma unroll 1
    for (int pass=0; pass<2; pass++){
      const int n8b = (pass<<6)+n8w;
      uint4* wzp = g_wz4 + ((size_t)(blockIdx.x*2+pass)*8)*256 + t;
      float acc[8][2][4];
      if (bstart){
        #pragma unroll
        for (int j=0;j<8;j++)
          #pragma unroll
          for (int m=0;m<2;m++){ acc[j][m][0]=0.f; acc[j][m][1]=0.f; acc[j][m][2]=0.f; acc[j][m][3]=0.f; }
        #pragma unroll 2
        for (int kc=0;kc<16;kc++)
          mma_chunk(acc,abase,kc<<4,kc,rowA,kadj,n8b,lane);
        #pragma unroll
        for (int j=0;j<8;j++){
          uint4 s;
          s.x = pk2f(acc[j][0][0],acc[j][0][1]);
          s.y = pk2f(acc[j][0][2],acc[j][0][3]);
          s.z = pk2f(acc[j][1][0],acc[j][1][1]);
          s.w = pk2f(acc[j][1][2],acc[j][1][3]);
          wzp[(size_t)j*256] = s;
        }
      } else {
        #pragma unroll
        for (int j=0;j<8;j++){
          uint4 s = wzp[(size_t)j*256];
          acc[j][0][0]=xlo(s.x); acc[j][0][1]=xhi(s.x);
          acc[j][0][2]=xlo(s.y); acc[j][0][3]=xhi(s.y);
          acc[j][1][0]=xlo(s.z); acc[j][1][1]=xhi(s.z);
          acc[j][1][2]=xlo(s.w); acc[j][1][3]=xhi(s.w);
        }
      }
      if (ss>0){
        #pragma unroll 2
        for (int kc=16;kc<32;kc++)
          mma_chunk(acc,abase,hin+((kc-16)<<4),kc,rowA,kadj,n8b,lane);
      }
      mma_chunk(acc,abase,768,32,rowA,kadj,n8b,lane);
      mma_chunk(acc,abase,784,33,rowA,kadj,n8b,lane);
      // epilogue
      #pragma unroll
      for (int j=0;j<8;j++){
        int n8=n8b+j;
        #pragma unroll
        for (int m=0;m<2;m++){
          float c0=acc[j][m][0],c1=acc[j][m][1],c2=acc[j][m][2],c3=acc[j][m][3];
          float t0=__shfl_xor_sync(~0u,c0,1), t1=__shfl_xor_sync(~0u,c1,1);
          float t2=__shfl_xor_sync(~0u,c2,1), t3=__shfl_xor_sync(~0u,c3,1);
          float gi_,gf_,gg_,go_; int row;
          if (lane&1){ gi_=t2; gf_=t3; gg_=c2; go_=c3; row=(m<<4)+(lane>>2)+8; }
          else       { gi_=c0; gf_=c1; gg_=t0; go_=t1; row=(m<<4)+(lane>>2); }
          int u=(n8<<1)|((lane>>1)&1);
          float cn = sigf(gf_)*Csm[row*CSTR+u] + sigf(gi_)*tanha(gg_);
          Csm[row*CSTR+u]=cn;
          A[row*ASTR+hout+u]=f2b(sigf(go_)*tanha(cn));
        }
      }
    }
    __syncthreads();

    const int branch=ss>>3, isM=ss&1, step=(ss>>1)&3;
    for (int rr=0;rr<4;rr++){
      int r=(wid<<2)+rr;
      const ush* hr = A + r*ASTR + hout;
      if (!isM){
        float a0=0.f,a1=0.f,a2=0.f,a3=0.f;
        #pragma unroll
        for (int kk=0;kk<8;kk++){
          int k=lane+(kk<<5); float hv=b2f(hr[k]);
          a0+=Wt[k]*hv; a1+=Wt[256+k]*hv; a2+=Wt[512+k]*hv; a3+=Wt[768+k]*hv;
        }
        #pragma unroll
        for (int o=16;o;o>>=1){
          a0+=__shfl_xor_sync(~0u,a0,o); a1+=__shfl_xor_sync(~0u,a1,o);
          a2+=__shfl_xor_sync(~0u,a2,o); a3+=__shfl_xor_sync(~0u,a3,o);
        }
        int mk=s_mask[r];
        float l0=(mk&1)?a0+bt[0]:NEGBIG, l1=(mk&2)?a1+bt[1]:NEGBIG;
        float l2=(mk&4)?a2+bt[2]:NEGBIG, l3=(mk&8)?a3+bt[3]:NEGBIG;
        float mx=fmaxf(fmaxf(l0,l1),fmaxf(l2,l3));
        float e0=__expf(l0-mx),e1=__expf(l1-mx),e2=__expf(l2-mx),e3=__expf(l3-mx);
        float se=e0+e1+e2+e3, sl=e0*l0+e1*l1+e2*l2+e3*l3, lse=mx+__logf(se);
        int ta=t_act[(size_t)(r0+r)*8+branch*4+step];
        float lsel=(ta==0)?l0:(ta==1)?l1:(ta==2)?l2:l3;
        if (lane==0){
          s_lp[r]+=lsel-lse; s_mask[r]=mk&~(1<<ta); eT+=lse-sl/se;
          A[r*ASTR+768+s_pidx[r]]=0; A[r*ASTR+768+ta]=0x3F80; s_pidx[r]=ta;
        }
      } else {
        float a[NMM];
        #pragma unroll
        for (int j=0;j<NMM;j++) a[j]=0.f;
        #pragma unroll
        for (int kk=0;kk<8;kk++){
          int k=lane+(kk<<5); float hv=b2f(hr[k]);
          #pragma unroll
          for (int j=0;j<NMM;j++) a[j]+=Wm[j*256+k]*hv;
        }
        #pragma unroll
        for (int j=0;j<NMM;j++)
          #pragma unroll
          for (int o=16;o;o>>=1) a[j]+=__shfl_xor_sync(~0u,a[j],o);
        float mx=-1e30f;
        #pragma unroll
        for (int j=0;j<NMM;j++){ a[j]+=bm[j]; mx=fmaxf(mx,a[j]); }
        float se=0.f,sl=0.f;
        #pragma unroll
        for (int j=0;j<NMM;j++){ float e=__expf(a[j]-mx); se+=e; sl+=e*a[j]; }
        float lse=mx+__logf(se);
        int ma=m_act[(size_t)(r0+r)*8+branch*4+step];
        float lsel=a[0];
        #pragma unroll
        for (int j=1;j<NMM;j++) lsel=(j==ma)?a[j]:lsel;
        if (lane==0){
          s_lp[r]+=lsel-lse; eM+=lse-sl/se;
          A[r*ASTR+768+s_pidx[r]]=0; A[r*ASTR+768+ma]=0x3F80; s_pidx[r]=ma;
        }
      }
    }
    if (ss<15 && t<RB){
      int sc=((ss>>3)<<1)|(ss&1), sn=(((ss+1)>>3)<<1)|((ss+1)&1);
      A[t*ASTR+784+sc]=0; A[t*ASTR+784+sn]=0x3F80;
    }
    if (ss==7){
      for (int i=t;i<RB*256;i+=NTH)
        A[(i>>8)*ASTR+(i&255)] = f2b(z2[(size_t)(r0+(i>>8))*256+(i&255)]);
      if (t<RB) s_mask[t]=15;
    }
  }

  __syncthreads();
  if (t<RB) out[r0+t]=s_lp[t];
  if (lane==0){ s_red[wid]=eT; s_red[8+wid]=eM; }
  __syncthreads();
  if (t==0){
    float sT=0.f,sM=0.f;
    for (int w=0;w<8;w++){ sT+=s_red[w]; sM+=s_red[8+w]; }
    atomicAdd(&g_ent[0],sT); atomicAdd(&g_ent[1],sM);
  }
}

__global__ void finalize_kernel(float* out,int off){
  if (threadIdx.x==0 && blockIdx.x==0){
    const float sc=1.0f/(65536.0f*8.0f);
    out[off]=g_ent[0]*sc; out[off+1]=g_ent[1]*sc;
  }
}
__global__ void cvt_kernel(const int* ti,const int* mi,float* out){
  int i=blockIdx.x*blockDim.x+threadIdx.x;
  if (i<65536*8){ out[65536+i]=(float)ti[i]; out[65536+65536*8+i]=(float)mi[i]; }
}

extern "C" void kernel_launch(void* const* d_in, const int* in_sizes, int n_in,
                              void* d_out, int out_size)
{
  (void)in_sizes; (void)n_in;
  const float* z1=(const float*)d_in[0];  const float* z2=(const float*)d_in[1];
  const int* t_act=(const int*)d_in[2];   const int* m_act=(const int*)d_in[3];
  const float* aemb=(const float*)d_in[4];const float* bemb=(const float*)d_in[5];
  const float* idemb=(const float*)d_in[6];
  const float* Wih=(const float*)d_in[7]; const float* Whh=(const float*)d_in[8];
  const float* bih=(const float*)d_in[9]; const float* bhh=(const float*)d_in[10];
  const float* Wt=(const float*)d_in[11]; const float* bt=(const float*)d_in[12];
  const float* Wm=(const float*)d_in[13]; const float* bm=(const float*)d_in[14];
  float* out=(float*)d_out;

  const int SMEM = RB*ASTR*2 + RB*CSTR*4;   // 51712 + 33024 = 84736 B -> 2 CTAs/SM
  cudaFuncSetAttribute(decoder_kernel, cudaFuncAttributeMaxDynamicSharedMemorySize, SMEM);

  prep_bfrag<<<(KC*64*32+255)/256,256>>>(Wih,Whh,aemb,bemb,idemb,bih,bhh);
  decoder_kernel<<<65536/RB, NTH, SMEM>>>(z1,z2,t_act,m_act,Wt,bt,Wm,bm,out);

  const int NACT=65536*8;
  if (out_size >= 65536+2*NACT+2){
    cvt_kernel<<<(NACT+255)/256,256>>>(t_act,m_act,out);
    finalize_kernel<<<1,32>>>(out,65536+2*NACT);
  } else if (out_size >= 65536+2){
    finalize_kernel<<<1,32>>>(out,65536);
  }
}